// round 12
// baseline (speedup 1.0000x reference)
#include <cuda_runtime.h>
#include <cuda_bf16.h>
#include <math.h>

#define B_     2
#define S_     2048
#define DM     1024
#define H_     16
#define DK     64
#define INNER_ 1024
#define NREL   4095   // relative positions -2047..2047

// ---------------- device scratch ----------------
__device__ float g_q[B_ * H_ * S_ * DK];     // [B,H,S,DK]
__device__ float g_k[B_ * H_ * S_ * DK];
__device__ float g_v[B_ * H_ * S_ * DK];
__device__ float g_ctx[B_ * S_ * INNER_];    // [B,S,H*DK]
__device__ float g_bias[H_ * NREL];          // bias per head per (k-q)+2047

// ---------------- bf16 helpers ----------------
__device__ __forceinline__ unsigned packbf(float x0, float x1) {
    __nv_bfloat162 t = __floats2bfloat162_rn(x0, x1);   // low = x0 (smaller k)
    return *reinterpret_cast<unsigned*>(&t);
}
// split pair (x0,x1) into packed hi (bf16) and packed lo (bf16 of residual)
__device__ __forceinline__ void split2(float x0, float x1,
                                       unsigned& h, unsigned& l) {
    float h0 = __bfloat162float(__float2bfloat16_rn(x0));
    float h1 = __bfloat162float(__float2bfloat16_rn(x1));
    h = packbf(h0, h1);
    l = packbf(x0 - h0, x1 - h1);
}

__device__ __forceinline__ void mma_bf16(float* c, unsigned a0, unsigned a1,
                                         unsigned a2, unsigned a3,
                                         unsigned b0, unsigned b1) {
    asm volatile(
        "mma.sync.aligned.m16n8k16.row.col.f32.bf16.bf16.f32 "
        "{%0,%1,%2,%3}, {%4,%5,%6,%7}, {%8,%9}, {%0,%1,%2,%3};\n"
        : "+f"(c[0]), "+f"(c[1]), "+f"(c[2]), "+f"(c[3])
        : "r"(a0), "r"(a1), "r"(a2), "r"(a3), "r"(b0), "r"(b1));
}

// 3-term: aH*bH + aH*bL + aL*bH  (~2^-17 effective product precision)
__device__ __forceinline__ void mma3(float* c, const unsigned* aH,
                                     const unsigned* aL, unsigned bH0,
                                     unsigned bH1, unsigned bL0, unsigned bL1) {
    mma_bf16(c, aH[0], aH[1], aH[2], aH[3], bH0, bH1);
    mma_bf16(c, aH[0], aH[1], aH[2], aH[3], bL0, bL1);
    mma_bf16(c, aL[0], aL[1], aL[2], aL[3], bH0, bH1);
}

// ---------------- relative position bias table ----------------
__global__ void bias_kernel(const float* __restrict__ table) {
    int idx = blockIdx.x * blockDim.x + threadIdx.x;
    if (idx >= H_ * NREL) return;
    int h   = idx / NREL;
    int rel = (idx % NREL) - 2047;      // rel = k - q
    int rb  = (rel > 0) ? 16 : 0;
    int r   = abs(rel);
    int v;
    if (r < 8) {
        v = r;
    } else {
        float t = logf((float)r * 0.125f) / 2.7725887f * 8.0f;
        v = 8 + (int)t;
        v = min(v, 15);
    }
    g_bias[idx] = table[(rb + v) * H_ + h];
}

// ---------------- 3xBF16 tensor-core GEMM 128x128x32, 2-stage pipelined ------
// mode 1: A=X, W selected by blockIdx.z (wq/wk/wv), permuted write to g_q/g_k/g_v
// mode 0: A=g_ctx, W=W0, plain row-major write to Copt
#define APITCH 20     // k-pair pitch for A tiles (16 pairs + pad)
#define BPITCH 136    // col pitch for B tiles
#define SA (128 * APITCH)
#define SB (16 * BPITCH)
#define STG (2 * SA + 2 * SB)
#define GEMM_SMEM (2 * STG * 4)

__global__ __launch_bounds__(256) void gemm_bf16x3(
    const float* __restrict__ X, const float* __restrict__ W0,
    const float* __restrict__ W1, const float* __restrict__ W2,
    float* __restrict__ Copt, int mode) {
    extern __shared__ unsigned smg[];

    const int K = 1024, N = 1024;
    int z = blockIdx.z;
    const float* A = (mode == 0) ? g_ctx : X;
    const float* W = (mode == 0) ? W0 : (z == 0 ? W0 : (z == 1 ? W1 : W2));

    int tid  = threadIdx.x;
    int warp = tid >> 5, lane = tid & 31;
    int g = lane >> 2, tig = lane & 3;
    int wm = (warp >> 2) * 64;
    int wn = (warp & 3) * 32;
    int bx = blockIdx.x, by = blockIdx.y;

    // per-thread load coordinates
    int ar = tid >> 3, acq = tid & 7;         // A: 4 chunks of (32 rows)
    int bp = tid >> 5, bcq = tid & 31;        // B: 2 chunks of (8 pairs)

    float acc[4][4][4];
#pragma unroll
    for (int mi = 0; mi < 4; mi++)
#pragma unroll
        for (int ni = 0; ni < 4; ni++)
#pragma unroll
            for (int c = 0; c < 4; c++) acc[mi][ni][c] = 0.0f;

    float4 aR[4], bR[4];

    // prefetch tile 0 and store to stage 0
#pragma unroll
    for (int i = 0; i < 4; i++)
        aR[i] = *(const float4*)(A + (size_t)(by * 128 + ar + i * 32) * K + acq * 4);
#pragma unroll
    for (int i = 0; i < 2; i++) {
        int p = bp + i * 8;
        bR[2 * i]     = *(const float4*)(W + (size_t)(2 * p) * N + bx * 128 + bcq * 4);
        bR[2 * i + 1] = *(const float4*)(W + (size_t)(2 * p + 1) * N + bx * 128 + bcq * 4);
    }
    {
        unsigned* AsH = smg;
        unsigned* AsL = AsH + SA;
        unsigned* BsH = AsL + SA;
        unsigned* BsL = BsH + SB;
#pragma unroll
        for (int i = 0; i < 4; i++) {
            uint2 h, l;
            split2(aR[i].x, aR[i].y, h.x, l.x);
            split2(aR[i].z, aR[i].w, h.y, l.y);
            *(uint2*)&AsH[(ar + i * 32) * APITCH + acq * 2] = h;
            *(uint2*)&AsL[(ar + i * 32) * APITCH + acq * 2] = l;
        }
#pragma unroll
        for (int i = 0; i < 2; i++) {
            int p = bp + i * 8;
            float4 ra = bR[2 * i], rb = bR[2 * i + 1];
            uint4 h, l;
            split2(ra.x, rb.x, h.x, l.x);
            split2(ra.y, rb.y, h.y, l.y);
            split2(ra.z, rb.z, h.z, l.z);
            split2(ra.w, rb.w, h.w, l.w);
            *(uint4*)&BsH[p * BPITCH + bcq * 4] = h;
            *(uint4*)&BsL[p * BPITCH + bcq * 4] = l;
        }
    }
    __syncthreads();

    for (int kt = 0; kt < K / 32; kt++) {
        int cur = kt & 1;
        unsigned* AsH = smg + cur * STG;
        unsigned* AsL = AsH + SA;
        unsigned* BsH = AsL + SA;
        unsigned* BsL = BsH + SB;

        // issue gmem prefetch for tile kt+1 (lands during compute)
        bool more = (kt + 1 < K / 32);
        if (more) {
            int k0 = (kt + 1) * 32;
#pragma unroll
            for (int i = 0; i < 4; i++)
                aR[i] = *(const float4*)(A + (size_t)(by * 128 + ar + i * 32) * K + k0 + acq * 4);
#pragma unroll
            for (int i = 0; i < 2; i++) {
                int p = bp + i * 8;
                bR[2 * i]     = *(const float4*)(W + (size_t)(k0 + 2 * p) * N + bx * 128 + bcq * 4);
                bR[2 * i + 1] = *(const float4*)(W + (size_t)(k0 + 2 * p + 1) * N + bx * 128 + bcq * 4);
            }
        }

        // compute on current stage: 2 k16 steps
#pragma unroll
        for (int ks = 0; ks < 2; ks++) {
            int kp = ks * 8;
            unsigned afH[4][4], afL[4][4], bfH[4][2], bfL[4][2];
#pragma unroll
            for (int mi = 0; mi < 4; mi++) {
                int r = wm + mi * 16 + g;
                afH[mi][0] = AsH[r * APITCH + kp + tig];
                afH[mi][1] = AsH[(r + 8) * APITCH + kp + tig];
                afH[mi][2] = AsH[r * APITCH + kp + tig + 4];
                afH[mi][3] = AsH[(r + 8) * APITCH + kp + tig + 4];
                afL[mi][0] = AsL[r * APITCH + kp + tig];
                afL[mi][1] = AsL[(r + 8) * APITCH + kp + tig];
                afL[mi][2] = AsL[r * APITCH + kp + tig + 4];
                afL[mi][3] = AsL[(r + 8) * APITCH + kp + tig + 4];
            }
#pragma unroll
            for (int ni = 0; ni < 4; ni++) {
                int c = wn + ni * 8 + g;
                bfH[ni][0] = BsH[(kp + tig) * BPITCH + c];
                bfH[ni][1] = BsH[(kp + tig + 4) * BPITCH + c];
                bfL[ni][0] = BsL[(kp + tig) * BPITCH + c];
                bfL[ni][1] = BsL[(kp + tig + 4) * BPITCH + c];
            }
#pragma unroll
            for (int mi = 0; mi < 4; mi++)
#pragma unroll
                for (int ni = 0; ni < 4; ni++)
                    mma3(acc[mi][ni], afH[mi], afL[mi], bfH[ni][0], bfH[ni][1],
                         bfL[ni][0], bfL[ni][1]);
        }

        // store prefetched tile into the other stage
        if (more) {
            unsigned* AsHn = smg + (1 - cur) * STG;
            unsigned* AsLn = AsHn + SA;
            unsigned* BsHn = AsLn + SA;
            unsigned* BsLn = BsHn + SB;
#pragma unroll
            for (int i = 0; i < 4; i++) {
                uint2 h, l;
                split2(aR[i].x, aR[i].y, h.x, l.x);
                split2(aR[i].z, aR[i].w, h.y, l.y);
                *(uint2*)&AsHn[(ar + i * 32) * APITCH + acq * 2] = h;
                *(uint2*)&AsLn[(ar + i * 32) * APITCH + acq * 2] = l;
            }
#pragma unroll
            for (int i = 0; i < 2; i++) {
                int p = bp + i * 8;
                float4 ra = bR[2 * i], rb = bR[2 * i + 1];
                uint4 h, l;
                split2(ra.x, rb.x, h.x, l.x);
                split2(ra.y, rb.y, h.y, l.y);
                split2(ra.z, rb.z, h.z, l.z);
                split2(ra.w, rb.w, h.w, l.w);
                *(uint4*)&BsHn[p * BPITCH + bcq * 4] = h;
                *(uint4*)&BsLn[p * BPITCH + bcq * 4] = l;
            }
            __syncthreads();
        }
    }

    // epilogue
    if (mode == 0) {
#pragma unroll
        for (int mi = 0; mi < 4; mi++)
#pragma unroll
            for (int ni = 0; ni < 4; ni++) {
                int r0 = by * 128 + wm + mi * 16 + g;
                int c0 = bx * 128 + wn + ni * 8 + tig * 2;
                *(float2*)(Copt + (size_t)r0 * N + c0) =
                    make_float2(acc[mi][ni][0], acc[mi][ni][1]);
                *(float2*)(Copt + (size_t)(r0 + 8) * N + c0) =
                    make_float2(acc[mi][ni][2], acc[mi][ni][3]);
            }
    } else {
        float* dst = (z == 0) ? g_q : (z == 1) ? g_k : g_v;
#pragma unroll
        for (int mi = 0; mi < 4; mi++)
#pragma unroll
            for (int ni = 0; ni < 4; ni++) {
                int r0 = by * 128 + wm + mi * 16 + g;
                int c0 = bx * 128 + wn + ni * 8 + tig * 2;
                int h = c0 >> 6, d = c0 & 63;
                {
                    int b = r0 >> 11, s = r0 & 2047;
                    *(float2*)(dst + (size_t)((b * H_ + h) * S_ + s) * DK + d) =
                        make_float2(acc[mi][ni][0], acc[mi][ni][1]);
                }
                {
                    int r1 = r0 + 8;
                    int b = r1 >> 11, s = r1 & 2047;
                    *(float2*)(dst + (size_t)((b * H_ + h) * S_ + s) * DK + d) =
                        make_float2(acc[mi][ni][2], acc[mi][ni][3]);
                }
            }
    }
}

// ------- 3xBF16 flash attention, 128x64 tiles, 8 warps, 2-stage K/V ---------
#define QP 36   // 32 d-pairs + pad
#define KP 36
#define VP 72   // 64 cols + pad (pair-rows)
#define PP 36
#define KVSTG (2 * 64 * KP + 2 * 32 * VP)    // one K/V stage (H+L), words
#define FLASH_SMEM ((2 * 128 * QP + 2 * 128 * PP + 2 * KVSTG + 2 * 192) * 4)

__global__ __launch_bounds__(256) void flash_bf16x3() {
    extern __shared__ unsigned smu[];
    unsigned* QsH = smu;                    // [128][36]
    unsigned* QsL = QsH + 128 * QP;
    unsigned* PsH = QsL + 128 * QP;         // [128][36]
    unsigned* PsL = PsH + 128 * PP;
    unsigned* kvbase = PsL + 128 * PP;      // 2 stages of K/V
    float* sBbase = (float*)(kvbase + 2 * KVSTG);  // 2 x 192 bias

    int qb = blockIdx.x, h = blockIdx.y, b = blockIdx.z;
    int tid  = threadIdx.x;
    int warp = tid >> 5, lane = tid & 31;
    int g = lane >> 2, tig = lane & 3;

    const float* Qg = g_q + ((size_t)(b * H_ + h) * S_ + qb * 128) * DK;
    const float* Kg = g_k + (size_t)(b * H_ + h) * S_ * DK;
    const float* Vg = g_v + (size_t)(b * H_ + h) * S_ * DK;

    // per-thread K/V load coords
    int kr = tid >> 4, kcq = tid & 15;      // K: 4 chunks of 16 rows
    int vp = tid >> 4, vcq = tid & 15;      // V: 2 chunks of 16 pairs

    // load Q tile (128x64)
#pragma unroll
    for (int i = 0; i < 8; i++) {
        int ch = tid + i * 256;
        int r = ch >> 4, cq = ch & 15;
        float4 v = *(const float4*)(Qg + (size_t)r * DK + cq * 4);
        uint2 hh, ll;
        split2(v.x, v.y, hh.x, ll.x);
        split2(v.z, v.w, hh.y, ll.y);
        *(uint2*)&QsH[r * QP + cq * 2] = hh;
        *(uint2*)&QsL[r * QP + cq * 2] = ll;
    }

    // prefetch + store K/V stage 0
    float4 kreg[4], vreg[4];
    float breg;
#pragma unroll
    for (int i = 0; i < 4; i++)
        kreg[i] = *(const float4*)(Kg + (size_t)(kr + i * 16) * DK + kcq * 4);
#pragma unroll
    for (int i = 0; i < 2; i++) {
        int p = vp + i * 16;
        vreg[2 * i]     = *(const float4*)(Vg + (size_t)(2 * p) * DK + vcq * 4);
        vreg[2 * i + 1] = *(const float4*)(Vg + (size_t)(2 * p + 1) * DK + vcq * 4);
    }
    breg = (tid < 191) ? g_bias[h * NREL + (-qb * 128) - 127 + 2047 + tid] : 0.0f;
    {
        unsigned* KsH = kvbase;
        unsigned* KsL = KsH + 64 * KP;
        unsigned* VsH = KsL + 64 * KP;
        unsigned* VsL = VsH + 32 * VP;
#pragma unroll
        for (int i = 0; i < 4; i++) {
            uint2 hh, ll;
            split2(kreg[i].x, kreg[i].y, hh.x, ll.x);
            split2(kreg[i].z, kreg[i].w, hh.y, ll.y);
            *(uint2*)&KsH[(kr + i * 16) * KP + kcq * 2] = hh;
            *(uint2*)&KsL[(kr + i * 16) * KP + kcq * 2] = ll;
        }
#pragma unroll
        for (int i = 0; i < 2; i++) {
            int p = vp + i * 16;
            float4 va = vreg[2 * i], vb = vreg[2 * i + 1];
            uint4 hh, ll;
            split2(va.x, vb.x, hh.x, ll.x);
            split2(va.y, vb.y, hh.y, ll.y);
            split2(va.z, vb.z, hh.z, ll.z);
            split2(va.w, vb.w, hh.w, ll.w);
            *(uint4*)&VsH[p * VP + vcq * 4] = hh;
            *(uint4*)&VsL[p * VP + vcq * 4] = ll;
        }
        if (tid < 191) sBbase[tid] = breg;
    }
    __syncthreads();

    float oacc[8][4];
#pragma unroll
    for (int ni = 0; ni < 8; ni++)
#pragma unroll
        for (int c = 0; c < 4; c++) oacc[ni][c] = 0.0f;
    float m_i[2] = {-1e30f, -1e30f}, l_i[2] = {0.0f, 0.0f};

    for (int kb = 0; kb < S_ / 64; kb++) {
        int cur = kb & 1;
        unsigned* KsH = kvbase + cur * KVSTG;
        unsigned* KsL = KsH + 64 * KP;
        unsigned* VsH = KsL + 64 * KP;
        unsigned* VsL = VsH + 32 * VP;
        float* sB = sBbase + cur * 192;
        bool more = (kb + 1 < S_ / 64);

        // prefetch next K/V + bias into regs
        if (more) {
            int kn = (kb + 1) * 64;
#pragma unroll
            for (int i = 0; i < 4; i++)
                kreg[i] = *(const float4*)(Kg + (size_t)(kn + kr + i * 16) * DK + kcq * 4);
#pragma unroll
            for (int i = 0; i < 2; i++) {
                int p = vp + i * 16;
                vreg[2 * i]     = *(const float4*)(Vg + (size_t)(kn + 2 * p) * DK + vcq * 4);
                vreg[2 * i + 1] = *(const float4*)(Vg + (size_t)(kn + 2 * p + 1) * DK + vcq * 4);
            }
            if (tid < 191)
                breg = g_bias[h * NREL + ((kb + 1) * 64 - qb * 128) - 127 + 2047 + tid];
        }

        // S = Q @ K^T  (warp: rows [16w,16w+16) x 64 cols)
        float sacc[8][4];
#pragma unroll
        for (int ni = 0; ni < 8; ni++)
#pragma unroll
            for (int c = 0; c < 4; c++) sacc[ni][c] = 0.0f;

#pragma unroll
        for (int ks = 0; ks < 4; ks++) {
            int kp = ks * 8;
            int rq = warp * 16 + g;
            unsigned aH[4], aL[4];
            aH[0] = QsH[rq * QP + kp + tig];
            aH[1] = QsH[(rq + 8) * QP + kp + tig];
            aH[2] = QsH[rq * QP + kp + tig + 4];
            aH[3] = QsH[(rq + 8) * QP + kp + tig + 4];
            aL[0] = QsL[rq * QP + kp + tig];
            aL[1] = QsL[(rq + 8) * QP + kp + tig];
            aL[2] = QsL[rq * QP + kp + tig + 4];
            aL[3] = QsL[(rq + 8) * QP + kp + tig + 4];
#pragma unroll
            for (int ni = 0; ni < 8; ni++) {
                int rk = ni * 8 + g;
                unsigned bH0 = KsH[rk * KP + kp + tig];
                unsigned bH1 = KsH[rk * KP + kp + tig + 4];
                unsigned bL0 = KsL[rk * KP + kp + tig];
                unsigned bL1 = KsL[rk * KP + kp + tig + 4];
                mma3(sacc[ni], aH, aL, bH0, bH1, bL0, bL1);
            }
        }

        // bias + online softmax (per half-row rh: rows g, g+8 of warp tile)
#pragma unroll
        for (int rh = 0; rh < 2; rh++) {
            int qr = warp * 16 + g + 8 * rh;
            float rm = -1e30f;
#pragma unroll
            for (int ni = 0; ni < 8; ni++) {
                int kc = ni * 8 + tig * 2;
                sacc[ni][2 * rh]     += sB[kc - qr + 127];
                sacc[ni][2 * rh + 1] += sB[kc + 1 - qr + 127];
                rm = fmaxf(rm, fmaxf(sacc[ni][2 * rh], sacc[ni][2 * rh + 1]));
            }
            rm = fmaxf(rm, __shfl_xor_sync(0xffffffffu, rm, 1));
            rm = fmaxf(rm, __shfl_xor_sync(0xffffffffu, rm, 2));
            float mn   = fmaxf(m_i[rh], rm);
            float corr = __expf(m_i[rh] - mn);
            float rs = 0.0f;
#pragma unroll
            for (int ni = 0; ni < 8; ni++) {
                float p0 = __expf(sacc[ni][2 * rh] - mn);
                float p1 = __expf(sacc[ni][2 * rh + 1] - mn);
                rs += p0 + p1;
                unsigned ph, pl;
                split2(p0, p1, ph, pl);
                PsH[qr * PP + ni * 4 + tig] = ph;
                PsL[qr * PP + ni * 4 + tig] = pl;
                oacc[ni][2 * rh]     *= corr;
                oacc[ni][2 * rh + 1] *= corr;
            }
            rs += __shfl_xor_sync(0xffffffffu, rs, 1);
            rs += __shfl_xor_sync(0xffffffffu, rs, 2);
            l_i[rh] = l_i[rh] * corr + rs;
            m_i[rh] = mn;
        }
        __syncwarp();   // P rows are warp-private

        // O += P @ V
#pragma unroll
        for (int ks = 0; ks < 4; ks++) {
            int kp = ks * 8;
            int pr = warp * 16 + g;
            unsigned aH[4], aL[4];
            aH[0] = PsH[pr * PP + kp + tig];
            aH[1] = PsH[(pr + 8) * PP + kp + tig];
            aH[2] = PsH[pr * PP + kp + tig + 4];
            aH[3] = PsH[(pr + 8) * PP + kp + tig + 4];
            aL[0] = PsL[pr * PP + kp + tig];
            aL[1] = PsL[(pr + 8) * PP + kp + tig];
            aL[2] = PsL[pr * PP + kp + tig + 4];
            aL[3] = PsL[(pr + 8) * PP + kp + tig + 4];
#pragma unroll
            for (int ni = 0; ni < 8; ni++) {
                int d = ni * 8 + g;
                unsigned bH0 = VsH[(kp + tig) * VP + d];
                unsigned bH1 = VsH[(kp + tig + 4) * VP + d];
                unsigned bL0 = VsL[(kp + tig) * VP + d];
                unsigned bL1 = VsL[(kp + tig + 4) * VP + d];
                mma3(oacc[ni], aH, aL, bH0, bH1, bL0, bL1);
            }
        }

        // store next K/V stage
        if (more) {
            unsigned* KsHn = kvbase + (1 - cur) * KVSTG;
            unsigned* KsLn = KsHn + 64 * KP;
            unsigned* VsHn = KsLn + 64 * KP;
            unsigned* VsLn = VsHn + 32 * VP;
#pragma unroll
            for (int i = 0; i < 4; i++) {
                uint2 hh, ll;
                split2(kreg[i].x, kreg[i].y, hh.x, ll.x);
                split2(kreg[i].z, kreg[i].w, hh.y, ll.y);
                *(uint2*)&KsHn[(kr + i * 16) * KP + kcq * 2] = hh;
                *(uint2*)&KsLn[(kr + i * 16) * KP + kcq * 2] = ll;
            }
#pragma unroll
            for (int i = 0; i < 2; i++) {
                int p = vp + i * 16;
                float4 va = vreg[2 * i], vb = vreg[2 * i + 1];
                uint4 hh, ll;
                split2(va.x, vb.x, hh.x, ll.x);
                split2(va.y, vb.y, hh.y, ll.y);
                split2(va.z, vb.z, hh.z, ll.z);
                split2(va.w, vb.w, hh.w, ll.w);
                *(uint4*)&VsHn[p * VP + vcq * 4] = hh;
                *(uint4*)&VsLn[p * VP + vcq * 4] = ll;
            }
            if (tid < 191) sBbase[(1 - cur) * 192 + tid] = breg;
        }
        __syncthreads();
    }

    // normalize + write ctx in [B,S,H*DK]
    float inv0 = 1.0f / l_i[0], inv1 = 1.0f / l_i[1];
#pragma unroll
    for (int ni = 0; ni < 8; ni++) {
        int q0 = qb * 128 + warp * 16 + g;
        int d0 = ni * 8 + tig * 2;
        *(float2*)(g_ctx + ((size_t)b * S_ + q0) * INNER_ + h * DK + d0) =
            make_float2(oacc[ni][0] * inv0, oacc[ni][1] * inv0);
        *(float2*)(g_ctx + ((size_t)b * S_ + q0 + 8) * INNER_ + h * DK + d0) =
            make_float2(oacc[ni][2] * inv1, oacc[ni][3] * inv1);
    }
}

// ---------------- launch ----------------
extern "C" void kernel_launch(void* const* d_in, const int* in_sizes, int n_in,
                              void* d_out, int out_size) {
    const float* X     = (const float*)d_in[0];
    const float* wq    = (const float*)d_in[1];
    const float* wk    = (const float*)d_in[2];
    const float* wv    = (const float*)d_in[3];
    const float* wo    = (const float*)d_in[4];
    const float* table = (const float*)d_in[5];
    float* out = (float*)d_out;

    cudaFuncSetAttribute(gemm_bf16x3,
                         cudaFuncAttributeMaxDynamicSharedMemorySize, GEMM_SMEM);
    cudaFuncSetAttribute(flash_bf16x3,
                         cudaFuncAttributeMaxDynamicSharedMemorySize, FLASH_SMEM);

    // 1. relative-position bias table
    bias_kernel<<<(H_ * NREL + 255) / 256, 256>>>(table);

    // 2. fused Q/K/V projections (grid.z selects weight + destination)
    dim3 gq(INNER_ / 128, (B_ * S_) / 128, 3);
    gemm_bf16x3<<<gq, 256, GEMM_SMEM>>>(X, wq, wk, wv, nullptr, 1);

    // 3. flash attention
    dim3 ga(S_ / 128, H_, B_);
    flash_bf16x3<<<ga, 256, FLASH_SMEM>>>();

    // 4. output projection
    dim3 go(DM / 128, (B_ * S_) / 128, 1);
    gemm_bf16x3<<<go, 256, GEMM_SMEM>>>(nullptr, wo, nullptr, nullptr, out, 0);
}